// round 4
// baseline (speedup 1.0000x reference)
#include <cuda_runtime.h>
#include <cstdint>

#define B_DIM 64
#define S_DIM 512
#define W_DIM 256
#define D_DIM 768
#define N_DIM 96
#define MT 64
#define KT 64
#define NUM_KT 12
#define THREADS 256

#define ROW_STRIDE 144              // bytes per bf16 tile row (64*2 + 16 pad)
#define OFF_AHI 0
#define OFF_ALO 9216                // 64 * 144
#define OFF_BHI 18432
#define OFF_BLO 32256               // 18432 + 96*144
#define STAGE   46080               // 32256 + 96*144
#define SM_TILES 1024
#define SMEM_TOTAL (SM_TILES + 2 * STAGE)

static __device__ __forceinline__ uint32_t smem_u32(const void* p) {
    uint32_t a;
    asm("{ .reg .u64 t; cvta.to.shared.u64 t, %1; cvt.u32.u64 %0, t; }" : "=r"(a) : "l"(p));
    return a;
}

static __device__ __forceinline__ void ldsm4(uint32_t* r, uint32_t addr) {
    asm volatile("ldmatrix.sync.aligned.m8n8.x4.shared.b16 {%0,%1,%2,%3}, [%4];"
                 : "=r"(r[0]), "=r"(r[1]), "=r"(r[2]), "=r"(r[3]) : "r"(addr));
}

static __device__ __forceinline__ void ldsm2(uint32_t* r, uint32_t addr) {
    asm volatile("ldmatrix.sync.aligned.m8n8.x2.shared.b16 {%0,%1}, [%2];"
                 : "=r"(r[0]), "=r"(r[1]) : "r"(addr));
}

static __device__ __forceinline__ void mma_bf16(float* c, const uint32_t* a, const uint32_t* b) {
    asm volatile(
        "mma.sync.aligned.m16n8k16.row.col.f32.bf16.bf16.f32 "
        "{%0,%1,%2,%3}, {%4,%5,%6,%7}, {%8,%9}, {%0,%1,%2,%3};"
        : "+f"(c[0]), "+f"(c[1]), "+f"(c[2]), "+f"(c[3])
        : "r"(a[0]), "r"(a[1]), "r"(a[2]), "r"(a[3]), "r"(b[0]), "r"(b[1]));
}

// fp32x4 -> hi bf16x2 pair + residual lo bf16x2 pair
static __device__ __forceinline__ void cvt_split(float4 v, uint2& hi, uint2& lo) {
    uint32_t h0, h1, l0, l1;
    asm("cvt.rn.bf16x2.f32 %0, %1, %2;" : "=r"(h0) : "f"(v.y), "f"(v.x));
    asm("cvt.rn.bf16x2.f32 %0, %1, %2;" : "=r"(h1) : "f"(v.w), "f"(v.z));
    float r0 = v.x - __uint_as_float(h0 << 16);
    float r1 = v.y - __uint_as_float(h0 & 0xffff0000u);
    float r2 = v.z - __uint_as_float(h1 << 16);
    float r3 = v.w - __uint_as_float(h1 & 0xffff0000u);
    asm("cvt.rn.bf16x2.f32 %0, %1, %2;" : "=r"(l0) : "f"(r1), "f"(r0));
    asm("cvt.rn.bf16x2.f32 %0, %1, %2;" : "=r"(l1) : "f"(r3), "f"(r2));
    hi.x = h0; hi.y = h1; lo.x = l0; lo.y = l1;
}

__global__ __launch_bounds__(THREADS, 2)
void ner_hmma_kernel(const float* __restrict__ seq, const int* __restrict__ widx,
                     const float* __restrict__ clsw, const float* __restrict__ clsb,
                     float* __restrict__ out) {
    extern __shared__ char smem[];
    const uint32_t sb = smem_u32(smem);
    const int tid  = threadIdx.x;
    const int wid  = tid >> 5;
    const int lane = tid & 31;
    const int b  = blockIdx.x >> 2;
    const int w0 = (blockIdx.x & 3) * MT;

    int* idx_s = (int*)smem;
    if (tid < MT) idx_s[tid] = widx[b * W_DIM + w0 + tid];
    __syncthreads();

    // ---- producer mapping: row-slot pr (0..15), float4 k-chunk pk ----
    const int pr = tid >> 4;           // 0..15
    const int pk = (tid & 15) << 2;    // float idx 0..60

    const float* aP[4];
#pragma unroll
    for (int i = 0; i < 4; i++)
        aP[i] = seq + ((size_t)b * S_DIM + idx_s[pr + 16 * i]) * D_DIM + pk;
    const float* bP[6];
#pragma unroll
    for (int i = 0; i < 6; i++)
        bP[i] = clsw + (size_t)(pr + 16 * i) * D_DIM + pk;

    uint32_t soA[4], soB[6];
#pragma unroll
    for (int i = 0; i < 4; i++) soA[i] = (uint32_t)(pr + 16 * i) * ROW_STRIDE + (uint32_t)pk * 2;
#pragma unroll
    for (int i = 0; i < 6; i++) soB[i] = (uint32_t)(pr + 16 * i) * ROW_STRIDE + (uint32_t)pk * 2;

    // ---- consumer mapping: 2(M) x 4(N) warp grid, warp tile 32x24 ----
    const int wm = (wid & 1) * 32;
    const int wn = (wid >> 1) * 24;

    const uint32_t aOff = (uint32_t)(wm + (lane & 15)) * ROW_STRIDE + ((lane >> 4) << 4);
    // B x4 (n-frags 0,1 -> 16 rows)
    const uint32_t bOff4 = (uint32_t)(wn + ((lane >> 4) << 3) + (lane & 7)) * ROW_STRIDE
                         + (((lane >> 3) & 1) << 4);
    // B x2 (n-frag 2 -> 8 rows, lanes 0..15 meaningful)
    const uint32_t bOff2 = (uint32_t)(wn + 16 + (lane & 7)) * ROW_STRIDE
                         + (((lane >> 3) & 1) << 4);

    float acc[6][4];
#pragma unroll
    for (int i = 0; i < 6; i++)
#pragma unroll
        for (int v = 0; v < 4; v++) acc[i][v] = 0.f;

    // prefetch tile 0
    float4 ra[4], rb[6];
#pragma unroll
    for (int i = 0; i < 4; i++) ra[i] = *(const float4*)(aP[i]);
#pragma unroll
    for (int i = 0; i < 6; i++) rb[i] = *(const float4*)(bP[i]);

    for (int t = 0; t < NUM_KT; t++) {
        const int p = t & 1;
        char* buf = smem + SM_TILES + p * STAGE;

        // convert + store current tile
#pragma unroll
        for (int i = 0; i < 4; i++) {
            uint2 hi, lo;
            cvt_split(ra[i], hi, lo);
            *(uint2*)(buf + OFF_AHI + soA[i]) = hi;
            *(uint2*)(buf + OFF_ALO + soA[i]) = lo;
        }
#pragma unroll
        for (int i = 0; i < 6; i++) {
            uint2 hi, lo;
            cvt_split(rb[i], hi, lo);
            *(uint2*)(buf + OFF_BHI + soB[i]) = hi;
            *(uint2*)(buf + OFF_BLO + soB[i]) = lo;
        }

        // prefetch next tile (overlaps compute)
        if (t + 1 < NUM_KT) {
            const int kg = (t + 1) * KT;
#pragma unroll
            for (int i = 0; i < 4; i++) ra[i] = *(const float4*)(aP[i] + kg);
#pragma unroll
            for (int i = 0; i < 6; i++) rb[i] = *(const float4*)(bP[i] + kg);
        }
        __syncthreads();

        const uint32_t sbuf = sb + SM_TILES + p * STAGE;
#pragma unroll
        for (int ks = 0; ks < 4; ks++) {
            const uint32_t k0b = (uint32_t)ks * 32;  // 16 bf16 = 32 B
            uint32_t ah[2][4], al[2][4];
#pragma unroll
            for (int i = 0; i < 2; i++) {
                ldsm4(ah[i], sbuf + OFF_AHI + aOff + i * (16 * ROW_STRIDE) + k0b);
                ldsm4(al[i], sbuf + OFF_ALO + aOff + i * (16 * ROW_STRIDE) + k0b);
            }
            uint32_t bh[6], bl[6];
            ldsm4(bh,     sbuf + OFF_BHI + bOff4 + k0b);
            ldsm2(bh + 4, sbuf + OFF_BHI + bOff2 + k0b);
            ldsm4(bl,     sbuf + OFF_BLO + bOff4 + k0b);
            ldsm2(bl + 4, sbuf + OFF_BLO + bOff2 + k0b);
#pragma unroll
            for (int i = 0; i < 2; i++)
#pragma unroll
                for (int j = 0; j < 3; j++) {
                    mma_bf16(acc[i * 3 + j], ah[i], &bh[j * 2]);
                    mma_bf16(acc[i * 3 + j], ah[i], &bl[j * 2]);
                    mma_bf16(acc[i * 3 + j], al[i], &bh[j * 2]);
                }
        }
        __syncthreads();
    }

    // ---- epilogue: scatter to out[a, b, w, c] ----
#pragma unroll
    for (int i = 0; i < 2; i++) {
#pragma unroll
        for (int j = 0; j < 3; j++) {
            const float* c = acc[i * 3 + j];
            const int n_base = wn + j * 8 + 2 * (lane & 3);
            const int m_base = wm + i * 16 + (lane >> 2);
#pragma unroll
            for (int v = 0; v < 4; v++) {
                const int n = n_base + (v & 1);
                const int m = m_base + (v >> 1) * 8;
                const int w = w0 + m;
                const int a_ = n / 3;
                const int c_ = n - a_ * 3;
                out[(size_t)a_ * (B_DIM * W_DIM * 3) + (size_t)b * (W_DIM * 3) + w * 3 + c_]
                    = c[v] + clsb[n];
            }
        }
    }
}

extern "C" void kernel_launch(void* const* d_in, const int* in_sizes, int n_in,
                              void* d_out, int out_size) {
    const float* seq  = (const float*)d_in[0];  // [B, S, D] fp32
    const int*   widx = (const int*)d_in[1];    // [B, W] int32
    const float* clsw = (const float*)d_in[2];  // [A*3, D] fp32
    const float* clsb = (const float*)d_in[3];  // [A*3] fp32
    float* out = (float*)d_out;                 // [A, B, W, 3] fp32

    cudaFuncSetAttribute(ner_hmma_kernel, cudaFuncAttributeMaxDynamicSharedMemorySize, SMEM_TOTAL);
    ner_hmma_kernel<<<256, THREADS, SMEM_TOTAL>>>(seq, widx, clsw, clsb, out);
}

// round 5
// speedup vs baseline: 1.6470x; 1.6470x over previous
#include <cuda_runtime.h>
#include <cstdint>

#define B_DIM 64
#define S_DIM 512
#define W_DIM 256
#define D_DIM 768
#define N_DIM 96
#define MT 64
#define KT 64
#define NUM_KT 12
#define THREADS 256

#define ROW_STRIDE 144              // bytes per fp16 tile row (64*2 + 16 pad)
#define OFF_A 0
#define OFF_B 9216                  // 64 * 144
#define STAGE 23040                 // 9216 + 96*144
#define SM_TILES 1024
#define SMEM_TOTAL (SM_TILES + 2 * STAGE)

static __device__ __forceinline__ uint32_t smem_u32(const void* p) {
    uint32_t a;
    asm("{ .reg .u64 t; cvta.to.shared.u64 t, %1; cvt.u32.u64 %0, t; }" : "=r"(a) : "l"(p));
    return a;
}

static __device__ __forceinline__ void ldsm4(uint32_t* r, uint32_t addr) {
    asm volatile("ldmatrix.sync.aligned.m8n8.x4.shared.b16 {%0,%1,%2,%3}, [%4];"
                 : "=r"(r[0]), "=r"(r[1]), "=r"(r[2]), "=r"(r[3]) : "r"(addr));
}

static __device__ __forceinline__ void ldsm2(uint32_t* r, uint32_t addr) {
    asm volatile("ldmatrix.sync.aligned.m8n8.x2.shared.b16 {%0,%1}, [%2];"
                 : "=r"(r[0]), "=r"(r[1]) : "r"(addr));
}

static __device__ __forceinline__ void mma_f16(float* c, const uint32_t* a, const uint32_t* b) {
    asm volatile(
        "mma.sync.aligned.m16n8k16.row.col.f32.f16.f16.f32 "
        "{%0,%1,%2,%3}, {%4,%5,%6,%7}, {%8,%9}, {%0,%1,%2,%3};"
        : "+f"(c[0]), "+f"(c[1]), "+f"(c[2]), "+f"(c[3])
        : "r"(a[0]), "r"(a[1]), "r"(a[2]), "r"(a[3]), "r"(b[0]), "r"(b[1]));
}

// fp32x4 -> packed fp16x4 (uint2); operand order matches prior passing kernels:
// low half of each word gets the lower-k element
static __device__ __forceinline__ uint2 cvt_f16x4(float4 v) {
    uint2 r;
    asm("cvt.rn.f16x2.f32 %0, %1, %2;" : "=r"(r.x) : "f"(v.y), "f"(v.x));
    asm("cvt.rn.f16x2.f32 %0, %1, %2;" : "=r"(r.y) : "f"(v.w), "f"(v.z));
    return r;
}

__global__ __launch_bounds__(THREADS, 2)
void ner_hmma_kernel(const float* __restrict__ seq, const int* __restrict__ widx,
                     const float* __restrict__ clsw, const float* __restrict__ clsb,
                     float* __restrict__ out) {
    extern __shared__ char smem[];
    const uint32_t sb = smem_u32(smem);
    const int tid  = threadIdx.x;
    const int wid  = tid >> 5;
    const int lane = tid & 31;
    const int b  = blockIdx.x >> 2;
    const int w0 = (blockIdx.x & 3) * MT;

    int* idx_s = (int*)smem;
    if (tid < MT) idx_s[tid] = widx[b * W_DIM + w0 + tid];
    __syncthreads();

    // ---- producer mapping: row-slot pr (0..15), float4 k-chunk pk ----
    const int pr = tid >> 4;           // 0..15
    const int pk = (tid & 15) << 2;    // float idx 0..60

    const float* aP[4];
#pragma unroll
    for (int i = 0; i < 4; i++)
        aP[i] = seq + ((size_t)b * S_DIM + idx_s[pr + 16 * i]) * D_DIM + pk;
    const float* bP[6];
#pragma unroll
    for (int i = 0; i < 6; i++)
        bP[i] = clsw + (size_t)(pr + 16 * i) * D_DIM + pk;

    uint32_t soA[4], soB[6];
#pragma unroll
    for (int i = 0; i < 4; i++) soA[i] = (uint32_t)(pr + 16 * i) * ROW_STRIDE + (uint32_t)pk * 2;
#pragma unroll
    for (int i = 0; i < 6; i++) soB[i] = (uint32_t)(pr + 16 * i) * ROW_STRIDE + (uint32_t)pk * 2;

    // ---- consumer mapping: 2(M) x 4(N) warp grid, warp tile 32x24 ----
    const int wm = (wid & 1) * 32;
    const int wn = (wid >> 1) * 24;

    const uint32_t aOff = (uint32_t)(wm + (lane & 15)) * ROW_STRIDE + ((lane >> 4) << 4);
    // B x4 (n-frags 0,1 -> 16 rows)
    const uint32_t bOff4 = (uint32_t)(wn + ((lane >> 4) << 3) + (lane & 7)) * ROW_STRIDE
                         + (((lane >> 3) & 1) << 4);
    // B x2 (n-frag 2 -> 8 rows; lanes 0..15 supply addresses)
    const uint32_t bOff2 = (uint32_t)(wn + 16 + (lane & 7)) * ROW_STRIDE
                         + (((lane >> 3) & 1) << 4);

    float acc[6][4];
#pragma unroll
    for (int i = 0; i < 6; i++)
#pragma unroll
        for (int v = 0; v < 4; v++) acc[i][v] = 0.f;

    // prefetch tile 0
    float4 ra[4], rb[6];
#pragma unroll
    for (int i = 0; i < 4; i++) ra[i] = *(const float4*)(aP[i]);
#pragma unroll
    for (int i = 0; i < 6; i++) rb[i] = *(const float4*)(bP[i]);

    for (int t = 0; t < NUM_KT; t++) {
        const int p = t & 1;
        char* buf = smem + SM_TILES + p * STAGE;

        // convert + store current tile (single fp16 tile, no lo)
#pragma unroll
        for (int i = 0; i < 4; i++) *(uint2*)(buf + OFF_A + soA[i]) = cvt_f16x4(ra[i]);
#pragma unroll
        for (int i = 0; i < 6; i++) *(uint2*)(buf + OFF_B + soB[i]) = cvt_f16x4(rb[i]);

        // prefetch next tile (LDG issued before barrier -> latency hidden)
        if (t + 1 < NUM_KT) {
            const int kg = (t + 1) * KT;
#pragma unroll
            for (int i = 0; i < 4; i++) ra[i] = *(const float4*)(aP[i] + kg);
#pragma unroll
            for (int i = 0; i < 6; i++) rb[i] = *(const float4*)(bP[i] + kg);
        }
        __syncthreads();   // single barrier per tile: orders stores(buf p) before reads,
                           // and (transitively) last tile's reads before next store of p

        const uint32_t sbuf = sb + SM_TILES + p * STAGE;
#pragma unroll
        for (int ks = 0; ks < 4; ks++) {
            const uint32_t k0b = (uint32_t)ks * 32;  // 16 fp16 = 32 B
            uint32_t af[2][4];
#pragma unroll
            for (int i = 0; i < 2; i++)
                ldsm4(af[i], sbuf + OFF_A + aOff + i * (16 * ROW_STRIDE) + k0b);
            uint32_t bf[6];
            ldsm4(bf,     sbuf + OFF_B + bOff4 + k0b);
            ldsm2(bf + 4, sbuf + OFF_B + bOff2 + k0b);
#pragma unroll
            for (int i = 0; i < 2; i++)
#pragma unroll
                for (int j = 0; j < 3; j++)
                    mma_f16(acc[i * 3 + j], af[i], &bf[j * 2]);
        }
    }

    // ---- epilogue: scatter to out[a, b, w, c] ----
#pragma unroll
    for (int i = 0; i < 2; i++) {
#pragma unroll
        for (int j = 0; j < 3; j++) {
            const float* c = acc[i * 3 + j];
            const int n_base = wn + j * 8 + 2 * (lane & 3);
            const int m_base = wm + i * 16 + (lane >> 2);
#pragma unroll
            for (int v = 0; v < 4; v++) {
                const int n = n_base + (v & 1);
                const int m = m_base + (v >> 1) * 8;
                const int w = w0 + m;
                const int a_ = n / 3;
                const int c_ = n - a_ * 3;
                out[(size_t)a_ * (B_DIM * W_DIM * 3) + (size_t)b * (W_DIM * 3) + w * 3 + c_]
                    = c[v] + clsb[n];
            }
        }
    }
}

extern "C" void kernel_launch(void* const* d_in, const int* in_sizes, int n_in,
                              void* d_out, int out_size) {
    const float* seq  = (const float*)d_in[0];  // [B, S, D] fp32
    const int*   widx = (const int*)d_in[1];    // [B, W] int32
    const float* clsw = (const float*)d_in[2];  // [A*3, D] fp32
    const float* clsb = (const float*)d_in[3];  // [A*3] fp32
    float* out = (float*)d_out;                 // [A, B, W, 3] fp32

    cudaFuncSetAttribute(ner_hmma_kernel, cudaFuncAttributeMaxDynamicSharedMemorySize, SMEM_TOTAL);
    ner_hmma_kernel<<<256, THREADS, SMEM_TOTAL>>>(seq, widx, clsw, clsb, out);
}

// round 6
// speedup vs baseline: 1.6497x; 1.0017x over previous
#include <cuda_runtime.h>
#include <cstdint>

#define B_DIM 64
#define S_DIM 512
#define W_DIM 256
#define D_DIM 768
#define N_DIM 96
#define MT 128
#define KT 64
#define NUM_KT 12
#define THREADS 256

#define ROW_STRIDE 144              // bytes per fp16 tile row (64*2 + 16 pad)
#define SM_A      1024              // after idx area
#define A_STAGE   18432             // 128 * 144
#define SM_B      (SM_A + 2 * A_STAGE)       // 37888
#define B_STAGE   13824             // 96 * 144
#define SMEM_TOTAL (SM_B + 3 * B_STAGE)      // 79360

// Pre-converted fp16 copy of clsw: [96][768] fp16, row stride 1536 B
__device__ __align__(16) unsigned char g_Bh[N_DIM * D_DIM * 2];

static __device__ __forceinline__ uint32_t smem_u32(const void* p) {
    uint32_t a;
    asm("{ .reg .u64 t; cvta.to.shared.u64 t, %1; cvt.u32.u64 %0, t; }" : "=r"(a) : "l"(p));
    return a;
}

static __device__ __forceinline__ void ldsm4(uint32_t* r, uint32_t addr) {
    asm volatile("ldmatrix.sync.aligned.m8n8.x4.shared.b16 {%0,%1,%2,%3}, [%4];"
                 : "=r"(r[0]), "=r"(r[1]), "=r"(r[2]), "=r"(r[3]) : "r"(addr));
}

static __device__ __forceinline__ void mma_f16(float* c, const uint32_t* a, const uint32_t* b) {
    asm volatile(
        "mma.sync.aligned.m16n8k16.row.col.f32.f16.f16.f32 "
        "{%0,%1,%2,%3}, {%4,%5,%6,%7}, {%8,%9}, {%0,%1,%2,%3};"
        : "+f"(c[0]), "+f"(c[1]), "+f"(c[2]), "+f"(c[3])
        : "r"(a[0]), "r"(a[1]), "r"(a[2]), "r"(a[3]), "r"(b[0]), "r"(b[1]));
}

static __device__ __forceinline__ uint2 cvt_f16x4(float4 v) {
    uint2 r;
    asm("cvt.rn.f16x2.f32 %0, %1, %2;" : "=r"(r.x) : "f"(v.y), "f"(v.x));
    asm("cvt.rn.f16x2.f32 %0, %1, %2;" : "=r"(r.y) : "f"(v.w), "f"(v.z));
    return r;
}

static __device__ __forceinline__ void cp16(uint32_t dst, const void* src) {
    asm volatile("cp.async.cg.shared.global [%0], [%1], 16;" :: "r"(dst), "l"(src) : "memory");
}

// ---------- kernel 1: convert clsw fp32 -> fp16 scratch ----------
__global__ void cvtB_kernel(const float* __restrict__ clsw) {
    int i = blockIdx.x * blockDim.x + threadIdx.x;   // 18432 float4 chunks
    float4 v = ((const float4*)clsw)[i];
    ((uint2*)g_Bh)[i] = cvt_f16x4(v);
}

// ---------- kernel 2: gathered GEMM ----------
__global__ __launch_bounds__(THREADS, 1)
void ner_hmma_kernel(const float* __restrict__ seq, const int* __restrict__ widx,
                     const float* __restrict__ clsb, float* __restrict__ out) {
    extern __shared__ char smem[];
    const uint32_t sb = smem_u32(smem);
    const int tid  = threadIdx.x;
    const int wid  = tid >> 5;
    const int lane = tid & 31;
    const int b  = blockIdx.x >> 1;
    const int w0 = (blockIdx.x & 1) * MT;

    int* idx_s = (int*)smem;
    if (tid < MT) idx_s[tid] = widx[b * W_DIM + w0 + tid];
    __syncthreads();

    // ---- producer A mapping: row-slot pr (0..15), float4 k-chunk pk ----
    const int pr = tid >> 4;
    const int pk = (tid & 15) << 2;

    const float* aP[8];
#pragma unroll
    for (int i = 0; i < 8; i++)
        aP[i] = seq + ((size_t)b * S_DIM + idx_s[pr + 16 * i]) * D_DIM + pk;

    uint32_t soA[8];
#pragma unroll
    for (int i = 0; i < 8; i++) soA[i] = (uint32_t)(pr + 16 * i) * ROW_STRIDE + (uint32_t)pk * 2;

    // ---- producer B mapping (cp.async): 3 tasks of 16B each ----
    // task u = tid + 256*j : row = u>>3 (0..95), chunk c = u&7
    uint32_t bDst[3];
    const unsigned char* bSrc[3];
#pragma unroll
    for (int j = 0; j < 3; j++) {
        int u = tid + 256 * j;
        int row = u >> 3, c = u & 7;
        bDst[j] = (uint32_t)row * ROW_STRIDE + (uint32_t)c * 16;
        bSrc[j] = g_Bh + (size_t)row * (D_DIM * 2) + c * 16;
    }

    // ---- consumer mapping: 4(M) x 2(N), warp tile 32x48 ----
    const int wm = (wid & 3) * 32;
    const int wn = (wid >> 2) * 48;

    const uint32_t aOff = (uint32_t)(wm + (lane & 15)) * ROW_STRIDE + ((lane >> 4) << 4);
    const uint32_t bOff = (uint32_t)(wn + ((lane >> 4) << 3) + (lane & 7)) * ROW_STRIDE
                        + (((lane >> 3) & 1) << 4);

    float acc[12][4];
#pragma unroll
    for (int i = 0; i < 12; i++)
#pragma unroll
        for (int v = 0; v < 4; v++) acc[i][v] = 0.f;

    // ---- prologue: tile 0 ----
    float4 ra[8];
#pragma unroll
    for (int i = 0; i < 8; i++) ra[i] = *(const float4*)(aP[i]);
#pragma unroll
    for (int j = 0; j < 3; j++) cp16(sb + SM_B + bDst[j], bSrc[j]);
    asm volatile("cp.async.commit_group;" ::: "memory");

    for (int t = 0; t < NUM_KT; t++) {
        const int p = t & 1;
        const int q = t % 3;
        char* bufA = smem + SM_A + p * A_STAGE;

        // convert + store A(t)
#pragma unroll
        for (int i = 0; i < 8; i++) *(uint2*)(bufA + soA[i]) = cvt_f16x4(ra[i]);

        if (t + 1 < NUM_KT) {
            const int kg = (t + 1) * KT;
#pragma unroll
            for (int i = 0; i < 8; i++) ra[i] = *(const float4*)(aP[i] + kg);
            const uint32_t bq = sb + SM_B + ((t + 1) % 3) * B_STAGE;
            const int kb = (t + 1) * (KT * 2);   // byte offset in g_Bh row
#pragma unroll
            for (int j = 0; j < 3; j++) cp16(bq + bDst[j], bSrc[j] + kb);
            asm volatile("cp.async.commit_group;" ::: "memory");
            asm volatile("cp.async.wait_group 1;" ::: "memory");
        } else {
            asm volatile("cp.async.wait_group 0;" ::: "memory");
        }
        __syncthreads();   // publishes A(t) stores + B(t) cp.async to all warps

        const uint32_t sA = sb + SM_A + p * A_STAGE;
        const uint32_t sB = sb + SM_B + q * B_STAGE;
#pragma unroll
        for (int ks = 0; ks < 4; ks++) {
            const uint32_t k0b = (uint32_t)ks * 32;
            uint32_t af[2][4];
#pragma unroll
            for (int i = 0; i < 2; i++)
                ldsm4(af[i], sA + aOff + i * (16 * ROW_STRIDE) + k0b);
            uint32_t bf[3][4];
#pragma unroll
            for (int j = 0; j < 3; j++)
                ldsm4(bf[j], sB + bOff + j * (16 * ROW_STRIDE) + k0b);
#pragma unroll
            for (int i = 0; i < 2; i++)
#pragma unroll
                for (int j2 = 0; j2 < 6; j2++)
                    mma_f16(acc[i * 6 + j2], af[i], &bf[j2 >> 1][(j2 & 1) * 2]);
        }
    }

    // ---- epilogue: scatter to out[a, b, w, c] ----
#pragma unroll
    for (int i = 0; i < 2; i++) {
#pragma unroll
        for (int j2 = 0; j2 < 6; j2++) {
            const float* c = acc[i * 6 + j2];
            const int n_base = wn + j2 * 8 + 2 * (lane & 3);
            const int m_base = wm + i * 16 + (lane >> 2);
#pragma unroll
            for (int v = 0; v < 4; v++) {
                const int n = n_base + (v & 1);
                const int m = m_base + (v >> 1) * 8;
                const int w = w0 + m;
                const int a_ = n / 3;
                const int c_ = n - a_ * 3;
                out[(size_t)a_ * (B_DIM * W_DIM * 3) + (size_t)b * (W_DIM * 3) + w * 3 + c_]
                    = c[v] + clsb[n];
            }
        }
    }
}

extern "C" void kernel_launch(void* const* d_in, const int* in_sizes, int n_in,
                              void* d_out, int out_size) {
    const float* seq  = (const float*)d_in[0];  // [B, S, D] fp32
    const int*   widx = (const int*)d_in[1];    // [B, W] int32
    const float* clsw = (const float*)d_in[2];  // [A*3, D] fp32
    const float* clsb = (const float*)d_in[3];  // [A*3] fp32
    float* out = (float*)d_out;                 // [A, B, W, 3] fp32

    cvtB_kernel<<<36, 512>>>(clsw);
    cudaFuncSetAttribute(ner_hmma_kernel, cudaFuncAttributeMaxDynamicSharedMemorySize, SMEM_TOTAL);
    ner_hmma_kernel<<<128, THREADS, SMEM_TOTAL>>>(seq, widx, clsb, out);
}